// round 5
// baseline (speedup 1.0000x reference)
#include <cuda_runtime.h>
#include <cuda_bf16.h>
#include <math.h>
#include <stdint.h>

// ---------------- problem constants ----------------
#define BB 8
#define TT 4096
#define DDIM 512
#define QQ 4
#define KCB 1024
#define NROWS (BB*TT)            // 32768
#define TOUT 2048

// d_out layout (floats), tuple order: y, quantized_out, indices, loss
#define Y_OFF    0
#define QO_OFF   (BB*TOUT*DDIM)                 //  8388608
#define IDX_OFF  (QO_OFF + BB*TT*DDIM)          // 25165824
#define LOSS_OFF (IDX_OFF + QQ*BB*TT)           // 25296896

typedef unsigned long long ull;

// ---------------- device scratch (no allocations allowed) ----------------
__device__ float  g_residual[(size_t)NROWS * DDIM];   // 64 MB
__device__ float  g_cnorm[QQ * KCB];
__device__ ull    g_wp[5 * 256 * 512];                // d-paired conv weights, 5.24 MB
__device__ double g_loss;

// ---------------- helpers ----------------
__device__ __forceinline__ ull fma2(ull a, ull b, ull c) {
    ull d;
    asm("fma.rn.f32x2 %0, %1, %2, %3;" : "=l"(d) : "l"(a), "l"(b), "l"(c));
    return d;
}
__device__ __forceinline__ ull pack2(float a, float b) {
    ull r;
    asm("mov.b64 %0, {%1, %2};" : "=l"(r) : "f"(a), "f"(b));
    return r;
}
__device__ __forceinline__ float2 unpk(ull v) {
    float2 f;
    asm("mov.b64 {%0, %1}, %2;" : "=f"(f.x), "=f"(f.y) : "l"(v));
    return f;
}
__device__ __forceinline__ void cpa8(unsigned s, const void* g) {
    asm volatile("cp.async.ca.shared.global [%0], [%1], 8;" :: "r"(s), "l"(g));
}
__device__ __forceinline__ void cpa8z(unsigned s, const void* g, int srcsz) {
    asm volatile("cp.async.ca.shared.global [%0], [%1], 8, %2;" :: "r"(s), "l"(g), "r"(srcsz));
}
__device__ __forceinline__ void cpa16(unsigned s, const void* g) {
    asm volatile("cp.async.ca.shared.global [%0], [%1], 16;" :: "r"(s), "l"(g));
}
#define CP_COMMIT() asm volatile("cp.async.commit_group;")
#define CP_WAIT1()  asm volatile("cp.async.wait_group 1;")
#define CP_WAIT0()  asm volatile("cp.async.wait_group 0;")

#define PA 130   // A smem pitch (ull units)
#define PB 66    // B smem pitch (ull units)
#define ABUF (8*PA*8)   // bytes per A stage
#define BBUF (8*PB*8)   // bytes per B stage

// inner micro-kernel: 8 d-pairs, 8 rows x 4 cols f32x2 accumulators (K-paired)
__device__ __forceinline__ void mma_chunk(const ull* __restrict__ sA,
                                          const ull* __restrict__ sB,
                                          ull acc[8][4], int ty, int tx) {
#pragma unroll
    for (int j = 0; j < 8; j++) {
        ull A[8], Bf[4];
        {
            const ulonglong2* ap = (const ulonglong2*)(sA + j * PA + ty * 8);
            ulonglong2 a0 = ap[0], a1 = ap[1], a2 = ap[2], a3 = ap[3];
            A[0] = a0.x; A[1] = a0.y; A[2] = a1.x; A[3] = a1.y;
            A[4] = a2.x; A[5] = a2.y; A[6] = a3.x; A[7] = a3.y;
        }
#pragma unroll
        for (int i = 0; i < 4; i++) Bf[i] = sB[j * PB + tx + 16 * i];
#pragma unroll
        for (int r = 0; r < 8; r++)
#pragma unroll
            for (int i = 0; i < 4; i++)
                acc[r][i] = fma2(A[r], Bf[i], acc[r][i]);
    }
}

// ---------------- codebook half-norms (0.5*||c||^2) ----------------
__global__ void cnorm_kernel(const float* __restrict__ codebooks) {
    int row  = blockIdx.x * 8 + (threadIdx.x >> 5);   // 4096 rows
    int lane = threadIdx.x & 31;
    const float4* c4 = (const float4*)(codebooks + (size_t)row * DDIM);
    float s = 0.0f;
#pragma unroll
    for (int i = 0; i < 4; i++) {
        float4 f = c4[lane + 32 * i];
        s += f.x * f.x + f.y * f.y + f.z * f.z + f.w * f.w;
    }
#pragma unroll
    for (int off = 16; off > 0; off >>= 1) s += __shfl_xor_sync(0xffffffffu, s, off);
    if (lane == 0) g_cnorm[row] = 0.5f * s;
}

// pre-pack conv weights into d-paired layout:
// g_wp[(k*256 + d2)*512 + n] = (w[k][2*d2][n], w[k][2*d2+1][n])
__global__ void wpack_kernel(const float* __restrict__ w) {
    int idx = blockIdx.x * 256 + threadIdx.x;      // 0 .. 655359
    int n   = idx & 511;
    int d2g = idx >> 9;                            // 0..1279
    int k   = d2g >> 8;
    int d2  = d2g & 255;
    float lo = w[((size_t)k * DDIM + 2 * d2) * DDIM + n];
    float hi = w[((size_t)k * DDIM + 2 * d2 + 1) * DDIM + n];
    g_wp[idx] = pack2(lo, hi);
}

__global__ void init_kernel() { g_loss = 0.0; }

__global__ void fin_kernel(float* __restrict__ out) {
    out[0] = (float)(0.25 * g_loss * (1.0 / (double)((size_t)NROWS * DDIM)));
}

// ---------------- VQ stage: GEMM + argmin + residual update ----------------
// grid 256 blocks (128 rows each), 256 threads, 2 CTAs/SM.
// Tile: 128 rows x 64 cols, 16 col-tiles. 3-stage cp.async pipeline.
__global__ void __launch_bounds__(256, 2) vq_stage_kernel(
    const float* __restrict__ x,
    const float* __restrict__ codebooks,
    float* __restrict__ qsum,
    float* __restrict__ idx_out,
    int qi)
{
    __shared__ __align__(16) ull sA[3][8 * PA];
    __shared__ __align__(16) ull sB[3][8 * PB];
    __shared__ float cns[KCB];
    __shared__ int   best_s[128];

    const int tid  = threadIdx.x;
    const int tx   = tid & 15, ty = tid >> 4;
    const int warp = tid >> 5, lane = tid & 31;
    const int Rb   = blockIdx.x * 128;

    const float* resin = qi ? g_residual : x;
    const float* cb    = codebooks + (size_t)qi * KCB * DDIM;
    const float* aRow  = resin + (size_t)Rb * DDIM;

    for (int i = tid; i < KCB; i += 256) cns[i] = g_cnorm[qi * KCB + i];

    // cp.async fill mapping: thread -> (j = tid&7, m-base = tid>>3)
    const int jF = tid & 7;
    const int mF = tid >> 3;           // 0..31
    const float* aF = aRow + (size_t)mF * DDIM + 2 * jF;
    const unsigned sAu = (unsigned)__cvta_generic_to_shared(&sA[0][0]);
    const unsigned sBu = (unsigned)__cvta_generic_to_shared(&sB[0][0]);
    const unsigned dA0 = sAu + (unsigned)(jF * PA + mF) * 8u;
    const unsigned dB0 = sBu + (unsigned)(jF * PB + mF) * 8u;

#define VQ_ISSUE(D0, BUF, BF) do {                                      \
        unsigned _da = dA0 + (unsigned)(BUF) * ABUF;                    \
        unsigned _db = dB0 + (unsigned)(BUF) * BBUF;                    \
        const float* _a = aF + (D0);                                    \
        const float* _b = (BF) + (D0);                                  \
        cpa8(_da,            _a);                                       \
        cpa8(_da + 32 * 8,   _a + 32 * DDIM);                           \
        cpa8(_da + 64 * 8,   _a + 64 * DDIM);                           \
        cpa8(_da + 96 * 8,   _a + 96 * DDIM);                           \
        cpa8(_db,            _b);                                       \
        cpa8(_db + 32 * 8,   _b + 32 * DDIM);                           \
        CP_COMMIT();                                                    \
    } while (0)

    float bv[8]; int bi[8];
#pragma unroll
    for (int r = 0; r < 8; r++) { bv[r] = 3.0e38f; bi[r] = 0; }

    for (int nt = 0; nt < 16; nt++) {
        const float* bF = cb + (size_t)(nt * 64 + mF) * DDIM + 2 * jF;

        ull acc[8][4];
#pragma unroll
        for (int r = 0; r < 8; r++)
#pragma unroll
            for (int i = 0; i < 4; i++) acc[r][i] = 0ull;

        // prologue: stages 0,1
        VQ_ISSUE(0,  0, bF);
        VQ_ISSUE(16, 1, bF);

        int bc = 0;                    // compute buffer = c % 3
        for (int c = 0; c < 32; c++) {
            if (c < 31) CP_WAIT1(); else CP_WAIT0();
            __syncthreads();
            if (c < 30) {
                int ib = bc + 2; if (ib >= 3) ib -= 3;
                VQ_ISSUE((c + 2) * 16, ib, bF);
            }
            mma_chunk(sA[bc], sB[bc], acc, ty, tx);
            bc = (bc == 2) ? 0 : bc + 1;
        }

        // per-tile argmin (first-min tie semantics, ascending cols)
#pragma unroll
        for (int r = 0; r < 8; r++) {
            float lbv = 3.0e38f; int lbi = 0;
#pragma unroll
            for (int i = 0; i < 4; i++) {
                float2 p = unpk(acc[r][i]);
                float s = p.x + p.y;
                int col = nt * 64 + tx + 16 * i;
                float vv = cns[col] - s;
                if (vv < lbv) { lbv = vv; lbi = col; }
            }
#pragma unroll
            for (int off = 1; off < 16; off <<= 1) {
                float ov = __shfl_xor_sync(0xffffffffu, lbv, off);
                int   oi = __shfl_xor_sync(0xffffffffu, lbi, off);
                if (ov < lbv || (ov == lbv && oi < lbi)) { lbv = ov; lbi = oi; }
            }
            if (lbv < bv[r] || (lbv == bv[r] && lbi < bi[r])) { bv[r] = lbv; bi[r] = lbi; }
        }
        __syncthreads();   // all smem readers done before next tile prologue
    }

    if (tx == 0) {
#pragma unroll
        for (int r = 0; r < 8; r++) best_s[ty * 8 + r] = bi[r];
    }
    __syncthreads();

    // fused epilogue: residual update, qsum accumulate, indices, loss
    double ls = 0.0;
    for (int rr = 0; rr < 16; rr++) {
        int row  = warp * 16 + rr;
        int gr   = Rb + row;
        int best = best_s[row];
        const float4* rp = (const float4*)(resin + (size_t)gr * DDIM);
        const float4* cp = (const float4*)(cb + (size_t)best * DDIM);
        float4* rw = (float4*)(g_residual + (size_t)gr * DDIM);
        float4* qw = (float4*)(qsum + (size_t)gr * DDIM);
        if (lane == 0) idx_out[qi * NROWS + gr] = (float)best;
#pragma unroll
        for (int it = 0; it < 4; it++) {
            int e = it * 32 + lane;
            float4 rv = rp[e], cv = cp[e];
            float4 nr = make_float4(rv.x - cv.x, rv.y - cv.y, rv.z - cv.z, rv.w - cv.w);
            ls += (double)(nr.x * nr.x + nr.y * nr.y + nr.z * nr.z + nr.w * nr.w);
            rw[e] = nr;
            if (qi == 0) {
                qw[e] = cv;
            } else {
                float4 o = qw[e];
                qw[e] = make_float4(o.x + cv.x, o.y + cv.y, o.z + cv.z, o.w + cv.w);
            }
        }
    }
#pragma unroll
    for (int off = 16; off > 0; off >>= 1) ls += __shfl_xor_sync(0xffffffffu, ls, off);
    if (lane == 0) atomicAdd(&g_loss, ls);
}

// ---------------- Conv1D (stride 2, SAME, K=5) + exact GELU ----------------
// Tile: 128 t_out x 64 n. grid (8 n-blocks, 128 m-blocks), 256 threads, 2 CTAs/SM.
// 3-stage cp.async pipeline; B from pre-packed g_wp; boundary via zero-fill.
__global__ void __launch_bounds__(256, 2) conv_kernel(
    const float* __restrict__ qo,
    float* __restrict__ y)
{
    __shared__ __align__(16) ull sA[3][8 * PA];
    __shared__ __align__(16) ull sB[3][8 * PB];

    const int tid = threadIdx.x;
    const int tx  = tid & 15, ty = tid >> 4;
    const int nb  = blockIdx.x;            // 0..7
    const int mb  = blockIdx.y;            // 0..127
    const int batch = mb >> 4;
    const int to0   = (mb & 15) * 128;
    const int n0    = nb * 64;

    const float* qb = qo + (size_t)batch * TT * DDIM;

    // cp.async fill mapping
    const int jF = tid & 7;
    const int mF = tid >> 3;               // 0..31
    const int jB = tid >> 5;               // 0..7  (B fill d-pair)
    const int cB = (tid & 31) * 2;         // 0..62 (B fill col base)
    const int trowB = 2 * (to0 + mF) - 1;
    const unsigned sAu = (unsigned)__cvta_generic_to_shared(&sA[0][0]);
    const unsigned sBu = (unsigned)__cvta_generic_to_shared(&sB[0][0]);
    const unsigned dA0 = sAu + (unsigned)(jF * PA + mF) * 8u;
    const unsigned dB0 = sBu + (unsigned)(jB * PB + cB) * 8u;

#define CV_ISSUE(CC, BUF) do {                                               \
        int _k = (CC) >> 5, _d0 = ((CC) & 31) * 16;                          \
        unsigned _da = dA0 + (unsigned)(BUF) * ABUF;                         \
        unsigned _db = dB0 + (unsigned)(BUF) * BBUF;                         \
        _Pragma("unroll")                                                    \
        for (int _s = 0; _s < 4; _s++) {                                     \
            int _t = trowB + 64 * _s + _k;                                   \
            int _ok = (_t >= 0 && _t < TT);                                  \
            const float* _src = _ok ? (qb + (size_t)_t * DDIM + _d0 + 2 * jF) : qb; \
            cpa8z(_da + _s * 32 * 8, _src, _ok ? 8 : 0);                     \
        }                                                                    \
        cpa16(_db, g_wp + ((size_t)(_k * 256 + ((CC) & 31) * 8 + jB)) * 512 + n0 + cB); \
        CP_COMMIT();                                                         \
    } while (0)

    ull acc[8][4];
#pragma unroll
    for (int r = 0; r < 8; r++)
#pragma unroll
        for (int i = 0; i < 4; i++) acc[r][i] = 0ull;

    // prologue: stages 0,1
    CV_ISSUE(0, 0);
    CV_ISSUE(1, 1);

    int bc = 0;
    for (int c = 0; c < 160; c++) {
        if (c < 159) CP_WAIT1(); else CP_WAIT0();
        __syncthreads();
        if (c < 158) {
            int ib = bc + 2; if (ib >= 3) ib -= 3;
            CV_ISSUE(c + 2, ib);
        }
        mma_chunk(sA[bc], sB[bc], acc, ty, tx);
        bc = (bc == 2) ? 0 : bc + 1;
    }

    // epilogue: horizontal add + exact GELU + store
#pragma unroll
    for (int r = 0; r < 8; r++) {
        int to = to0 + ty * 8 + r;
        float* yp = y + ((size_t)batch * TOUT + to) * DDIM + n0;
#pragma unroll
        for (int i = 0; i < 4; i++) {
            float2 p = unpk(acc[r][i]);
            float s = p.x + p.y;
            float g = 0.5f * s * (1.0f + erff(s * 0.70710678118654752f));
            yp[tx + 16 * i] = g;
        }
    }
}

// ---------------- launch ----------------
extern "C" void kernel_launch(void* const* d_in, const int* in_sizes, int n_in,
                              void* d_out, int out_size) {
    (void)in_sizes; (void)n_in; (void)out_size;
    const float* x   = (const float*)d_in[0];
    const float* cbs = (const float*)d_in[1];
    const float* w   = (const float*)d_in[2];
    float* out  = (float*)d_out;
    float* y    = out + Y_OFF;
    float* qo   = out + QO_OFF;
    float* idx  = out + IDX_OFF;
    float* loss = out + LOSS_OFF;

    cnorm_kernel<<<KCB * QQ / 8, 256>>>(cbs);
    wpack_kernel<<<2560, 256>>>(w);
    init_kernel<<<1, 1>>>();
    for (int qi = 0; qi < QQ; qi++)
        vq_stage_kernel<<<NROWS / 128, 256>>>(x, cbs, qo, idx, qi);
    fin_kernel<<<1, 1>>>(loss);
    conv_kernel<<<dim3(8, 128), 256>>>(qo, y);
}

// round 10
// speedup vs baseline: 2.2722x; 2.2722x over previous
#include <cuda_runtime.h>
#include <cuda_bf16.h>
#include <math.h>
#include <stdint.h>

#define BB 8
#define TT 4096
#define DDIM 512
#define QQ 4
#define KCB 1024
#define NROWS (BB*TT)
#define TOUT 2048

#define Y_OFF    0
#define QO_OFF   (BB*TOUT*DDIM)
#define IDX_OFF  (QO_OFF + BB*TT*DDIM)
#define LOSS_OFF (IDX_OFF + QQ*BB*TT)

typedef __nv_bfloat16 bf16;

__device__ float  g_residual[(size_t)NROWS * DDIM];
__device__ float  g_cnorm[QQ * KCB];
__device__ double g_loss;
__device__ __align__(16) bf16 g_xh[(size_t)NROWS * DDIM];
__device__ __align__(16) bf16 g_xl[(size_t)NROWS * DDIM];
__device__ __align__(16) bf16 g_rh[(size_t)NROWS * DDIM];
__device__ __align__(16) bf16 g_rl[(size_t)NROWS * DDIM];
__device__ __align__(16) bf16 g_qh[(size_t)NROWS * DDIM];
__device__ __align__(16) bf16 g_ql[(size_t)NROWS * DDIM];
__device__ __align__(16) bf16 g_cbh[(size_t)QQ * KCB * DDIM];
__device__ __align__(16) bf16 g_cbl[(size_t)QQ * KCB * DDIM];
__device__ __align__(16) bf16 g_wth[(size_t)DDIM * 5 * DDIM];   // [n][k*512+d]
__device__ __align__(16) bf16 g_wtl[(size_t)DDIM * 5 * DDIM];

__device__ __forceinline__ uint32_t smem_u32(const void* p) {
    return (uint32_t)__cvta_generic_to_shared(p);
}
__device__ __forceinline__ void cpa16(uint32_t s, const void* g) {
    asm volatile("cp.async.ca.shared.global [%0], [%1], 16;" :: "r"(s), "l"(g));
}
__device__ __forceinline__ void cpa16z(uint32_t s, const void* g, int sz) {
    asm volatile("cp.async.ca.shared.global [%0], [%1], 16, %2;" :: "r"(s), "l"(g), "r"(sz));
}
#define CP_COMMIT() asm volatile("cp.async.commit_group;")
#define CP_WAIT1()  asm volatile("cp.async.wait_group 1;")
#define CP_WAIT0()  asm volatile("cp.async.wait_group 0;")

__device__ __forceinline__ void ldsm4(uint32_t* r, uint32_t a) {
    asm volatile("ldmatrix.sync.aligned.m8n8.x4.shared.b16 {%0,%1,%2,%3}, [%4];"
                 : "=r"(r[0]), "=r"(r[1]), "=r"(r[2]), "=r"(r[3]) : "r"(a));
}
__device__ __forceinline__ void mma_bf16(float* c, const uint32_t* a, const uint32_t* b) {
    asm volatile(
        "mma.sync.aligned.m16n8k16.row.col.f32.bf16.bf16.f32 "
        "{%0,%1,%2,%3},{%4,%5,%6,%7},{%8,%9},{%0,%1,%2,%3};"
        : "+f"(c[0]), "+f"(c[1]), "+f"(c[2]), "+f"(c[3])
        : "r"(a[0]), "r"(a[1]), "r"(a[2]), "r"(a[3]), "r"(b[0]), "r"(b[1]));
}
__device__ __forceinline__ float gelu1(float s) {
    return 0.5f * s * (1.0f + erff(s * 0.70710678118654752f));
}

// smem layout: rows padded to 80B (32 bf16 data + 8 pad)
#define PITCH 80
#define ARR   10240              // 128 rows * 80B
#define STG   40960              // Ah,Al,Bh,Bl
#define OFF_CNS  0
#define OFF_SV   4096
#define OFF_SI   5120
#define OFF_BEST 6144
#define OFF_BUF  6656
#define SMEM_VQ (OFF_BUF + 3*STG)   // 129536
#define SMEM_CV (3*STG)             // 122880

// ---------------- small kernels ----------------
__global__ void cnorm_kernel(const float* __restrict__ codebooks) {
    int row  = blockIdx.x * 8 + (threadIdx.x >> 5);
    int lane = threadIdx.x & 31;
    const float4* c4 = (const float4*)(codebooks + (size_t)row * DDIM);
    float s = 0.0f;
#pragma unroll
    for (int i = 0; i < 4; i++) {
        float4 f = c4[lane + 32 * i];
        s += f.x * f.x + f.y * f.y + f.z * f.z + f.w * f.w;
    }
#pragma unroll
    for (int off = 16; off > 0; off >>= 1) s += __shfl_xor_sync(0xffffffffu, s, off);
    if (lane == 0) g_cnorm[row] = 0.5f * s;
}

__device__ __forceinline__ void dec1(float v, bf16& h, bf16& l) {
    h = __float2bfloat16(v);
    l = __float2bfloat16(v - __bfloat162float(h));
}
__global__ void decomp_x_kernel(const float* __restrict__ x) {
    size_t i = (size_t)blockIdx.x * 256 + threadIdx.x;
    bf16 h, l; dec1(x[i], h, l);
    g_xh[i] = h; g_xl[i] = l;
}
__global__ void decomp_cb_kernel(const float* __restrict__ cbs) {
    size_t i = (size_t)blockIdx.x * 256 + threadIdx.x;
    bf16 h, l; dec1(cbs[i], h, l);
    g_cbh[i] = h; g_cbl[i] = l;
}
__global__ void wtdecomp_kernel(const float* __restrict__ w) {
    int n = blockIdx.x;
    for (int kd = threadIdx.x; kd < 5 * DDIM; kd += 256) {
        int k = kd >> 9, d = kd & 511;
        float v = w[((size_t)k * DDIM + d) * DDIM + n];
        bf16 h, l; dec1(v, h, l);
        g_wth[(size_t)n * (5 * DDIM) + kd] = h;
        g_wtl[(size_t)n * (5 * DDIM) + kd] = l;
    }
}
__global__ void init_kernel() { g_loss = 0.0; }
__global__ void fin_kernel(float* __restrict__ out) {
    out[0] = (float)(0.25 * g_loss * (1.0 / (double)((size_t)NROWS * DDIM)));
}

// shared inner compute: one 32-wide k-chunk for the 128x128 CTA tile
__device__ __forceinline__ void chunk_mma(
    uint32_t sb, const uint32_t aA[2], const uint32_t bB[4], float acc[2][8][4])
{
#pragma unroll
    for (int ks = 0; ks < 2; ks++) {
        uint32_t ah[2][4], al[2][4], bh[8][2], bl[8][2];
        ldsm4(ah[0], aA[0] + sb + ks * 32);
        ldsm4(ah[1], aA[1] + sb + ks * 32);
        ldsm4(al[0], aA[0] + sb + ARR + ks * 32);
        ldsm4(al[1], aA[1] + sb + ARR + ks * 32);
#pragma unroll
        for (int p = 0; p < 4; p++) {
            uint32_t t4[4];
            ldsm4(t4, bB[p] + sb + ks * 32);
            bh[2*p][0] = t4[0]; bh[2*p][1] = t4[1];
            bh[2*p+1][0] = t4[2]; bh[2*p+1][1] = t4[3];
            ldsm4(t4, bB[p] + sb + ARR + ks * 32);
            bl[2*p][0] = t4[0]; bl[2*p][1] = t4[1];
            bl[2*p+1][0] = t4[2]; bl[2*p+1][1] = t4[3];
        }
#pragma unroll
        for (int mf = 0; mf < 2; mf++)
#pragma unroll
            for (int nf = 0; nf < 8; nf++) {
                mma_bf16(acc[mf][nf], ah[mf], bh[nf]);
                mma_bf16(acc[mf][nf], ah[mf], bl[nf]);
                mma_bf16(acc[mf][nf], al[mf], bh[nf]);
            }
    }
}

// ---------------- VQ stage ----------------
__global__ void __launch_bounds__(256, 1)
vq_mma_kernel(const float* __restrict__ x, const float* __restrict__ cbs,
              float* __restrict__ qsum, float* __restrict__ idx_out, int qi)
{
    extern __shared__ __align__(16) char sm[];
    float* cns    = (float*)(sm + OFF_CNS);
    float* sv     = (float*)(sm + OFF_SV);
    int*   si     = (int*)(sm + OFF_SI);
    int*   best_s = (int*)(sm + OFF_BEST);
    const uint32_t bufb = smem_u32(sm + OFF_BUF);

    const int tid = threadIdx.x, wid = tid >> 5, lane = tid & 31;
    const int mw = wid & 3, nw = wid >> 2;
    const int Rb = blockIdx.x * 128;

    const bf16* Ahg = ((qi == 0) ? g_xh : g_rh) + (size_t)Rb * DDIM;
    const bf16* Alg = ((qi == 0) ? g_xl : g_rl) + (size_t)Rb * DDIM;
    const bf16* Bh0 = g_cbh + (size_t)qi * KCB * DDIM;
    const bf16* Bl0 = g_cbl + (size_t)qi * KCB * DDIM;
    bf16* Dh = (qi < 3) ? g_rh : g_qh;
    bf16* Dl = (qi < 3) ? g_rl : g_ql;

    for (int i = tid; i < KCB; i += 256) cns[i] = g_cnorm[qi * KCB + i];

    const int lm = tid >> 1, seg = tid & 1;
    const uint32_t dstA = bufb + (uint32_t)(lm * PITCH + seg * 32);

    uint32_t aA[2], bB[4];
#pragma unroll
    for (int mf = 0; mf < 2; mf++)
        aA[mf] = bufb + (uint32_t)((mw * 32 + mf * 16 + (lane & 15)) * PITCH + (lane >> 4) * 16);
    {
        int st = lane >> 3;
        int rr = (lane & 7) + ((st & 2) ? 8 : 0);
        int cb = (st & 1) * 16;
#pragma unroll
        for (int p = 0; p < 4; p++)
            bB[p] = bufb + (uint32_t)(2 * ARR + (nw * 64 + p * 16 + rr) * PITCH + cb);
    }

#define VQ_ISS(C, S) do {                                                  \
        uint32_t _d = dstA + (uint32_t)(S) * STG;                          \
        size_t _ao = (size_t)lm * DDIM + (C) * 32 + seg * 16;              \
        cpa16(_d,            Ahg + _ao);  cpa16(_d + 16,           Ahg + _ao + 8); \
        cpa16(_d + ARR,      Alg + _ao);  cpa16(_d + ARR + 16,     Alg + _ao + 8); \
        size_t _bo = (size_t)(ntB + lm) * DDIM + (C) * 32 + seg * 16;      \
        cpa16(_d + 2*ARR,    Bh0 + _bo);  cpa16(_d + 2*ARR + 16,   Bh0 + _bo + 8); \
        cpa16(_d + 3*ARR,    Bl0 + _bo);  cpa16(_d + 3*ARR + 16,   Bl0 + _bo + 8); \
        CP_COMMIT();                                                       \
    } while (0)

    float bv[2][2]; int bi[2][2];
#pragma unroll
    for (int a = 0; a < 2; a++)
#pragma unroll
        for (int b = 0; b < 2; b++) { bv[a][b] = 3.0e38f; bi[a][b] = 0; }

    for (int nt = 0; nt < 8; nt++) {
        const int ntB = nt * 128;
        float acc[2][8][4];
#pragma unroll
        for (int mf = 0; mf < 2; mf++)
#pragma unroll
            for (int nf = 0; nf < 8; nf++)
#pragma unroll
                for (int e = 0; e < 4; e++) acc[mf][nf][e] = 0.0f;

        VQ_ISS(0, 0); VQ_ISS(1, 1);
        for (int c = 0; c < 16; c++) {
            if (c < 15) CP_WAIT1(); else CP_WAIT0();
            __syncthreads();
            if (c < 14) { int s2 = (c + 2) % 3; VQ_ISS(c + 2, s2); }
            chunk_mma((uint32_t)((c % 3) * STG), aA, bB, acc);
        }

#pragma unroll
        for (int mf = 0; mf < 2; mf++)
#pragma unroll
            for (int h = 0; h < 2; h++)
#pragma unroll
                for (int nf = 0; nf < 8; nf++)
#pragma unroll
                    for (int e = 0; e < 2; e++) {
                        int col = ntB + nw * 64 + nf * 8 + (lane & 3) * 2 + e;
                        float vv = cns[col] - acc[mf][nf][h * 2 + e];
                        if (vv < bv[mf][h]) { bv[mf][h] = vv; bi[mf][h] = col; }
                    }
        __syncthreads();   // all stage-buffer reads done before next prologue
    }

    // cross-lane / cross-warp argmin combine
#pragma unroll
    for (int mf = 0; mf < 2; mf++)
#pragma unroll
        for (int h = 0; h < 2; h++) {
            float v = bv[mf][h]; int ix = bi[mf][h];
#pragma unroll
            for (int o = 1; o < 4; o <<= 1) {
                float ov = __shfl_xor_sync(0xffffffffu, v, o);
                int   oi = __shfl_xor_sync(0xffffffffu, ix, o);
                if (ov < v || (ov == v && oi < ix)) { v = ov; ix = oi; }
            }
            if ((lane & 3) == 0) {
                int row = mw * 32 + mf * 16 + h * 8 + (lane >> 2);
                sv[nw * 128 + row] = v; si[nw * 128 + row] = ix;
            }
        }
    __syncthreads();
    if (tid < 128) {
        float v0 = sv[tid], v1 = sv[128 + tid];
        int   i0 = si[tid], i1 = si[128 + tid];
        best_s[tid] = (v1 < v0 || (v1 == v0 && i1 < i0)) ? i1 : i0;
    }
    __syncthreads();

    // exact fp32 epilogue: residual, qsum, indices, loss + hi/lo decomposition
    const float* resin = qi ? g_residual : x;
    const float* cb    = cbs + (size_t)qi * KCB * DDIM;
    double ls = 0.0;
    for (int rr = 0; rr < 16; rr++) {
        int row  = wid * 16 + rr;
        int gr   = Rb + row;
        int best = best_s[row];
        const float4* rp = (const float4*)(resin + (size_t)gr * DDIM);
        const float4* cp = (const float4*)(cb + (size_t)best * DDIM);
        float4* rw = (float4*)(g_residual + (size_t)gr * DDIM);
        float4* qw = (float4*)(qsum + (size_t)gr * DDIM);
        ushort4* hw = (ushort4*)((unsigned short*)Dh + (size_t)gr * DDIM);
        ushort4* lw = (ushort4*)((unsigned short*)Dl + (size_t)gr * DDIM);
        if (lane == 0) idx_out[qi * NROWS + gr] = (float)best;
#pragma unroll
        for (int it = 0; it < 4; it++) {
            int e = it * 32 + lane;
            float4 rv = rp[e], cv = cp[e];
            float4 nr = make_float4(rv.x - cv.x, rv.y - cv.y, rv.z - cv.z, rv.w - cv.w);
            ls += (double)(nr.x * nr.x + nr.y * nr.y + nr.z * nr.z + nr.w * nr.w);
            float4 q4;
            if (qi == 0) q4 = cv;
            else { float4 o = qw[e]; q4 = make_float4(o.x + cv.x, o.y + cv.y, o.z + cv.z, o.w + cv.w); }
            qw[e] = q4;
            if (qi < 3) rw[e] = nr;
            float4 dv = (qi < 3) ? nr : q4;
            bf16 h0, l0, h1, l1, h2, l2, h3, l3;
            dec1(dv.x, h0, l0); dec1(dv.y, h1, l1); dec1(dv.z, h2, l2); dec1(dv.w, h3, l3);
            ushort4 hh, llv;
            hh.x  = __bfloat16_as_ushort(h0); hh.y  = __bfloat16_as_ushort(h1);
            hh.z  = __bfloat16_as_ushort(h2); hh.w  = __bfloat16_as_ushort(h3);
            llv.x = __bfloat16_as_ushort(l0); llv.y = __bfloat16_as_ushort(l1);
            llv.z = __bfloat16_as_ushort(l2); llv.w = __bfloat16_as_ushort(l3);
            hw[e] = hh; lw[e] = llv;
        }
    }
#pragma unroll
    for (int off = 16; off > 0; off >>= 1) ls += __shfl_xor_sync(0xffffffffu, ls, off);
    if (lane == 0) atomicAdd(&g_loss, ls);
}

// ---------------- Conv1D (mma) + exact GELU ----------------
__global__ void __launch_bounds__(256, 1)
conv_mma_kernel(float* __restrict__ y)
{
    extern __shared__ __align__(16) char sm[];
    const uint32_t bufb = smem_u32(sm);

    const int tid = threadIdx.x, wid = tid >> 5, lane = tid & 31;
    const int mw = wid & 3, nw = wid >> 2;
    const int batch = blockIdx.x >> 4;
    const int to0   = (blockIdx.x & 15) * 128;

    const bf16* Qh = g_qh + (size_t)batch * TT * DDIM;
    const bf16* Ql = g_ql + (size_t)batch * TT * DDIM;

    const int lm = tid >> 1, seg = tid & 1;
    const uint32_t dstA = bufb + (uint32_t)(lm * PITCH + seg * 32);

    uint32_t aA[2], bB[4];
#pragma unroll
    for (int mf = 0; mf < 2; mf++)
        aA[mf] = bufb + (uint32_t)((mw * 32 + mf * 16 + (lane & 15)) * PITCH + (lane >> 4) * 16);
    {
        int st = lane >> 3;
        int rr = (lane & 7) + ((st & 2) ? 8 : 0);
        int cb = (st & 1) * 16;
#pragma unroll
        for (int p = 0; p < 4; p++)
            bB[p] = bufb + (uint32_t)(2 * ARR + (nw * 64 + p * 16 + rr) * PITCH + cb);
    }

#define CV_ISS(C, S) do {                                                   \
        int _kt = (C) >> 4, _d0 = ((C) & 15) * 32;                          \
        uint32_t _d = dstA + (uint32_t)(S) * STG;                           \
        int _tin = 2 * (to0 + lm) - 1 + _kt;                                \
        int _ok = (_tin >= 0 && _tin < TT);                                 \
        size_t _ao = (size_t)(_ok ? _tin : 0) * DDIM + _d0 + seg * 16;      \
        cpa16z(_d,            Qh + _ao,     _ok ? 16 : 0);                  \
        cpa16z(_d + 16,       Qh + _ao + 8, _ok ? 16 : 0);                  \
        cpa16z(_d + ARR,      Ql + _ao,     _ok ? 16 : 0);                  \
        cpa16z(_d + ARR + 16, Ql + _ao + 8, _ok ? 16 : 0);                  \
        size_t _bo = (size_t)(ntB + lm) * (5 * DDIM) + (C) * 32 + seg * 16; \
        cpa16(_d + 2*ARR,      g_wth + _bo);                                \
        cpa16(_d + 2*ARR + 16, g_wth + _bo + 8);                            \
        cpa16(_d + 3*ARR,      g_wtl + _bo);                                \
        cpa16(_d + 3*ARR + 16, g_wtl + _bo + 8);                            \
        CP_COMMIT();                                                        \
    } while (0)

    for (int nt = 0; nt < 4; nt++) {
        const int ntB = nt * 128;
        float acc[2][8][4];
#pragma unroll
        for (int mf = 0; mf < 2; mf++)
#pragma unroll
            for (int nf = 0; nf < 8; nf++)
#pragma unroll
                for (int e = 0; e < 4; e++) acc[mf][nf][e] = 0.0f;

        CV_ISS(0, 0); CV_ISS(1, 1);
        for (int c = 0; c < 80; c++) {
            if (c < 79) CP_WAIT1(); else CP_WAIT0();
            __syncthreads();
            if (c < 78) { int s2 = (c + 2) % 3; CV_ISS(c + 2, s2); }
            chunk_mma((uint32_t)((c % 3) * STG), aA, bB, acc);
        }

        // GELU + store
#pragma unroll
        for (int mf = 0; mf < 2; mf++) {
            int r0 = to0 + mw * 32 + mf * 16 + (lane >> 2);
#pragma unroll
            for (int nf = 0; nf < 8; nf++) {
                int col = ntB + nw * 64 + nf * 8 + (lane & 3) * 2;
                float* y0 = y + ((size_t)batch * TOUT + r0) * DDIM + col;
                float* y1 = y + ((size_t)batch * TOUT + r0 + 8) * DDIM + col;
                float2 g0 = make_float2(gelu1(acc[mf][nf][0]), gelu1(acc[mf][nf][1]));
                float2 g1 = make_float2(gelu1(acc[mf][nf][2]), gelu1(acc[mf][nf][3]));
                *(float2*)y0 = g0;
                *(float2*)y1 = g1;
            }
        }
        __syncthreads();
    }
}

// ---------------- launch ----------------
extern "C" void kernel_launch(void* const* d_in, const int* in_sizes, int n_in,
                              void* d_out, int out_size) {
    (void)in_sizes; (void)n_in; (void)out_size;
    const float* x   = (const float*)d_in[0];
    const float* cbs = (const float*)d_in[1];
    const float* w   = (const float*)d_in[2];
    float* out  = (float*)d_out;
    float* y    = out + Y_OFF;
    float* qo   = out + QO_OFF;
    float* idx  = out + IDX_OFF;
    float* loss = out + LOSS_OFF;

    cudaFuncSetAttribute(vq_mma_kernel,   cudaFuncAttributeMaxDynamicSharedMemorySize, SMEM_VQ);
    cudaFuncSetAttribute(conv_mma_kernel, cudaFuncAttributeMaxDynamicSharedMemorySize, SMEM_CV);

    cnorm_kernel<<<KCB * QQ / 8, 256>>>(cbs);
    decomp_x_kernel<<<NROWS * DDIM / 256, 256>>>(x);
    decomp_cb_kernel<<<QQ * KCB * DDIM / 256, 256>>>(cbs);
    wtdecomp_kernel<<<DDIM, 256>>>(w);
    init_kernel<<<1, 1>>>();
    for (int qi = 0; qi < QQ; qi++)
        vq_mma_kernel<<<NROWS / 128, 256, SMEM_VQ>>>(x, cbs, qo, idx, qi);
    fin_kernel<<<1, 1>>>(loss);
    conv_mma_kernel<<<BB * 16, 256, SMEM_CV>>>(y);
}